// round 5
// baseline (speedup 1.0000x reference)
#include <cuda_runtime.h>
#include <cstdint>

#define T_STEPS 2048
#define BATCH   64
#define HID     256
#define MROWS   (T_STEPS * BATCH)   // 131072
#define NGW     20                  // GEMM worker CTAs (148 - 128)
#define NCHUNK  1024                // 2-timestep chunks of 128 rows
#define NTILE   (NCHUNK * 2)        // (chunk, 128-wide n-tile) work items

// GEMM smem layout constants (per buffer)
#define GBK          16
#define AS_K_STRIDE  192            // floats per k-row: 16 groups * 12
#define WD_K_STRIDE  160            // u64  per k-row: 16 groups * 10
#define AS_BYTES     (GBK * AS_K_STRIDE * 4)   // 12288
#define WD_BYTES     (GBK * WD_K_STRIDE * 8)   // 20480
#define GEMM_SMEM    (2 * (AS_BYTES + WD_BYTES))  // 65536

__device__ float g_buf0[(size_t)MROWS * HID];   // xp0
__device__ float g_buf1[(size_t)MROWS * HID];   // h1
__device__ float g_buf2[(size_t)MROWS * HID];   // xp1
__device__ int   g_prog1[BATCH];                // layer-1 progress (t+1)
__device__ int   g_midflag[NTILE];              // xp1 tile-done flags

// ---------------------------------------------------------------------------
union F4U { float4 v; unsigned long long u[2]; };

__device__ __forceinline__ unsigned long long ffma2(
    unsigned long long a, unsigned long long b, unsigned long long c)
{
    unsigned long long d;
    asm("fma.rn.f32x2 %0, %1, %2, %3;" : "=l"(d) : "l"(a), "l"(b), "l"(c));
    return d;
}
__device__ __forceinline__ unsigned long long pk2(float lo, float hi)
{
    unsigned long long r;
    asm("mov.b64 %0, {%1, %2};" : "=l"(r) : "f"(lo), "f"(hi));
    return r;
}
__device__ __forceinline__ float2 up2(unsigned long long v)
{
    float2 r;
    asm("mov.b64 {%0, %1}, %2;" : "=f"(r.x), "=f"(r.y) : "l"(v));
    return r;
}
__device__ __forceinline__ int ld_acq(const int* p)
{
    int v;
    asm volatile("ld.acquire.gpu.global.b32 %0, [%1];" : "=r"(v) : "l"(p) : "memory");
    return v;
}
__device__ __forceinline__ void st_rel(int* p, int v)
{
    asm volatile("st.release.gpu.global.b32 [%0], %1;" :: "l"(p), "r"(v) : "memory");
}

// ---------------------------------------------------------------------------
// 128x128 GEMM tile: C[128, bn:bn+128] = A[128,256] @ W^T + (b1+b2)
// 256 threads, 8x8 per thread, FFMA2 with W pre-duplicated into f32x2 pairs
// at SMEM-store time. Single-barrier double buffering. Conflict-free reads.
// ---------------------------------------------------------------------------
__device__ __forceinline__ void gemm_tile128(
    const float* __restrict__ Arows,   // 128x256 row block
    const float* __restrict__ W,       // [256,256] row-major
    const float* __restrict__ b1,
    const float* __restrict__ b2,
    float* __restrict__ Crows,         // 128x256 row block
    int bn,                            // 0 or 128
    char* smembase)
{
    float* Asb[2];
    unsigned long long* Wdb[2];
    Asb[0] = reinterpret_cast<float*>(smembase);
    Asb[1] = reinterpret_cast<float*>(smembase + AS_BYTES);
    Wdb[0] = reinterpret_cast<unsigned long long*>(smembase + 2 * AS_BYTES);
    Wdb[1] = reinterpret_cast<unsigned long long*>(smembase + 2 * AS_BYTES + WD_BYTES);

    const int tid = threadIdx.x;
    const int row = tid >> 1;          // 0..127 (both A row and W row)
    const int k8  = (tid & 1) * 8;     // k-half within 16-wide tile
    const int tx  = tid & 15;          // n-group (8 cols)
    const int ty  = tid >> 4;          // m-group (8 rows)

    const float* aptr = Arows + (size_t)row * 256 + k8;
    const float* wptr = W + (size_t)(bn + row) * 256 + k8;
    const int agrp = (row >> 3) * 12 + (row & 7);
    const int wgrp = (row >> 3) * 10 + (row & 7);

    float4 ra0, ra1, rw0, rw1;

    // Prologue: load + store k-tile 0
    ra0 = *reinterpret_cast<const float4*>(aptr);
    ra1 = *reinterpret_cast<const float4*>(aptr + 4);
    rw0 = *reinterpret_cast<const float4*>(wptr);
    rw1 = *reinterpret_cast<const float4*>(wptr + 4);
    {
        float* As = Asb[0];
        unsigned long long* Wd = Wdb[0];
        As[(k8+0)*AS_K_STRIDE + agrp] = ra0.x;
        As[(k8+1)*AS_K_STRIDE + agrp] = ra0.y;
        As[(k8+2)*AS_K_STRIDE + agrp] = ra0.z;
        As[(k8+3)*AS_K_STRIDE + agrp] = ra0.w;
        As[(k8+4)*AS_K_STRIDE + agrp] = ra1.x;
        As[(k8+5)*AS_K_STRIDE + agrp] = ra1.y;
        As[(k8+6)*AS_K_STRIDE + agrp] = ra1.z;
        As[(k8+7)*AS_K_STRIDE + agrp] = ra1.w;
        Wd[(k8+0)*WD_K_STRIDE + wgrp] = pk2(rw0.x, rw0.x);
        Wd[(k8+1)*WD_K_STRIDE + wgrp] = pk2(rw0.y, rw0.y);
        Wd[(k8+2)*WD_K_STRIDE + wgrp] = pk2(rw0.z, rw0.z);
        Wd[(k8+3)*WD_K_STRIDE + wgrp] = pk2(rw0.w, rw0.w);
        Wd[(k8+4)*WD_K_STRIDE + wgrp] = pk2(rw1.x, rw1.x);
        Wd[(k8+5)*WD_K_STRIDE + wgrp] = pk2(rw1.y, rw1.y);
        Wd[(k8+6)*WD_K_STRIDE + wgrp] = pk2(rw1.z, rw1.z);
        Wd[(k8+7)*WD_K_STRIDE + wgrp] = pk2(rw1.w, rw1.w);
    }
    __syncthreads();

    unsigned long long acc2[4][8];
    #pragma unroll
    for (int mp = 0; mp < 4; mp++)
        #pragma unroll
        for (int n = 0; n < 8; n++) acc2[mp][n] = 0ull;

    for (int kt = 0; kt < 16; kt++) {
        if (kt < 15) {
            const float* ap = aptr + (kt + 1) * 16;
            const float* wp = wptr + (kt + 1) * 16;
            ra0 = *reinterpret_cast<const float4*>(ap);
            ra1 = *reinterpret_cast<const float4*>(ap + 4);
            rw0 = *reinterpret_cast<const float4*>(wp);
            rw1 = *reinterpret_cast<const float4*>(wp + 4);
        }

        const float* As = Asb[kt & 1];
        const unsigned long long* Wd = Wdb[kt & 1];

        #pragma unroll
        for (int k = 0; k < GBK; k++) {
            F4U am0, am1;
            am0.v = *reinterpret_cast<const float4*>(&As[k*AS_K_STRIDE + ty*12]);
            am1.v = *reinterpret_cast<const float4*>(&As[k*AS_K_STRIDE + ty*12 + 4]);
            const unsigned long long* wr = &Wd[k*WD_K_STRIDE + tx*10];
            F4U w01, w23, w45, w67;
            w01.v = *reinterpret_cast<const float4*>(wr);
            w23.v = *reinterpret_cast<const float4*>(wr + 2);
            w45.v = *reinterpret_cast<const float4*>(wr + 4);
            w67.v = *reinterpret_cast<const float4*>(wr + 6);
            unsigned long long wn[8] = { w01.u[0], w01.u[1], w23.u[0], w23.u[1],
                                         w45.u[0], w45.u[1], w67.u[0], w67.u[1] };
            unsigned long long am[4] = { am0.u[0], am0.u[1], am1.u[0], am1.u[1] };
            #pragma unroll
            for (int mp = 0; mp < 4; mp++)
                #pragma unroll
                for (int n = 0; n < 8; n++)
                    acc2[mp][n] = ffma2(am[mp], wn[n], acc2[mp][n]);
        }

        if (kt < 15) {
            float* Asn = Asb[(kt + 1) & 1];
            unsigned long long* Wdn = Wdb[(kt + 1) & 1];
            Asn[(k8+0)*AS_K_STRIDE + agrp] = ra0.x;
            Asn[(k8+1)*AS_K_STRIDE + agrp] = ra0.y;
            Asn[(k8+2)*AS_K_STRIDE + agrp] = ra0.z;
            Asn[(k8+3)*AS_K_STRIDE + agrp] = ra0.w;
            Asn[(k8+4)*AS_K_STRIDE + agrp] = ra1.x;
            Asn[(k8+5)*AS_K_STRIDE + agrp] = ra1.y;
            Asn[(k8+6)*AS_K_STRIDE + agrp] = ra1.z;
            Asn[(k8+7)*AS_K_STRIDE + agrp] = ra1.w;
            Wdn[(k8+0)*WD_K_STRIDE + wgrp] = pk2(rw0.x, rw0.x);
            Wdn[(k8+1)*WD_K_STRIDE + wgrp] = pk2(rw0.y, rw0.y);
            Wdn[(k8+2)*WD_K_STRIDE + wgrp] = pk2(rw0.z, rw0.z);
            Wdn[(k8+3)*WD_K_STRIDE + wgrp] = pk2(rw0.w, rw0.w);
            Wdn[(k8+4)*WD_K_STRIDE + wgrp] = pk2(rw1.x, rw1.x);
            Wdn[(k8+5)*WD_K_STRIDE + wgrp] = pk2(rw1.y, rw1.y);
            Wdn[(k8+6)*WD_K_STRIDE + wgrp] = pk2(rw1.z, rw1.z);
            Wdn[(k8+7)*WD_K_STRIDE + wgrp] = pk2(rw1.w, rw1.w);
            __syncthreads();
        }
    }

    float bias[8];
    #pragma unroll
    for (int n = 0; n < 8; n++) {
        int col = bn + tx * 8 + n;
        bias[n] = b1[col] + b2[col];
    }

    #pragma unroll
    for (int mp = 0; mp < 4; mp++) {
        float2 p[8];
        #pragma unroll
        for (int n = 0; n < 8; n++) p[n] = up2(acc2[mp][n]);
        int row0 = ty * 8 + 2 * mp;
        float4 o;
        o.x = p[0].x + bias[0]; o.y = p[1].x + bias[1];
        o.z = p[2].x + bias[2]; o.w = p[3].x + bias[3];
        *reinterpret_cast<float4*>(&Crows[(size_t)row0*256 + bn + tx*8]) = o;
        o.x = p[4].x + bias[4]; o.y = p[5].x + bias[5];
        o.z = p[6].x + bias[6]; o.w = p[7].x + bias[7];
        *reinterpret_cast<float4*>(&Crows[(size_t)row0*256 + bn + tx*8 + 4]) = o;
        o.x = p[0].y + bias[0]; o.y = p[1].y + bias[1];
        o.z = p[2].y + bias[2]; o.w = p[3].y + bias[3];
        *reinterpret_cast<float4*>(&Crows[(size_t)(row0+1)*256 + bn + tx*8]) = o;
        o.x = p[4].y + bias[4]; o.y = p[5].y + bias[5];
        o.z = p[6].y + bias[6]; o.w = p[7].y + bias[7];
        *reinterpret_cast<float4*>(&Crows[(size_t)(row0+1)*256 + bn + tx*8 + 4]) = o;
    }
}

// ---------------------------------------------------------------------------
__global__ __launch_bounds__(256) void gemm_bias_kernel(
    const float* __restrict__ A, const float* __restrict__ W,
    const float* __restrict__ b1, const float* __restrict__ b2,
    float* __restrict__ C)
{
    extern __shared__ char sm[];
    gemm_tile128(A + (size_t)blockIdx.x * 128 * 256, W, b1, b2,
                 C + (size_t)blockIdx.x * 128 * 256, blockIdx.y * 128, sm);
}

__global__ void zero_flags_kernel()
{
    int t = threadIdx.x;
    if (t < BATCH) g_prog1[t] = 0;
    for (int i = t; i < NTILE; i += blockDim.x) g_midflag[i] = 0;
}

// ---------------------------------------------------------------------------
// Scan role: one CTA per batch element. W row j: 128 floats in regs,
// 128 in smem. Double-buffered h, 1 barrier per step.
// ---------------------------------------------------------------------------
__device__ __forceinline__ void scan_role(
    const float* __restrict__ xp, const float* __restrict__ Whh,
    float* __restrict__ out, int b,
    int* prog_out, const int* poll_flags,
    float4* Wt)
{
    __shared__ __align__(16) float hbuf[2][HID];
    const int j = threadIdx.x;

    unsigned long long w2[64];
    const float4* wrow = reinterpret_cast<const float4*>(Whh + (size_t)j * HID);
    #pragma unroll
    for (int i = 0; i < 32; i++) {
        F4U v; v.v = wrow[i];
        w2[2*i] = v.u[0]; w2[2*i+1] = v.u[1];
    }
    #pragma unroll
    for (int i = 0; i < 32; i++)
        Wt[j * 33 + i] = wrow[32 + i];

    hbuf[0][j] = 0.f;
    __syncthreads();

    const float4* wsrow  = &Wt[j * 33];
    const float*  xptr   = xp  + (size_t)b * HID + j;
    float*        optr   = out + (size_t)b * HID + j;
    const size_t  stride = (size_t)BATCH * HID;

    int cur = 0;
    for (int t = 0; t < T_STEPS; t++) {
        if (poll_flags && (t & 1) == 0) {
            int c = t >> 1;
            if (j < 2)
                while (ld_acq(&poll_flags[c * 2 + j]) == 0) __nanosleep(100);
            __syncthreads();
        }

        float xv = xptr[(size_t)t * stride];

        const float4* h4 = reinterpret_cast<const float4*>(hbuf[cur]);
        unsigned long long a0 = 0ull, a1 = 0ull, a2 = 0ull, a3 = 0ull;

        #pragma unroll
        for (int i = 0; i < 32; i += 2) {      // k in [0,128): W in regs
            F4U hv0; hv0.v = h4[i];
            a0 = ffma2(w2[2*i],   hv0.u[0], a0);
            a1 = ffma2(w2[2*i+1], hv0.u[1], a1);
            F4U hv1; hv1.v = h4[i+1];
            a2 = ffma2(w2[2*i+2], hv1.u[0], a2);
            a3 = ffma2(w2[2*i+3], hv1.u[1], a3);
        }
        #pragma unroll
        for (int i = 0; i < 32; i += 2) {      // k in [128,256): W in smem
            F4U wv0; wv0.v = wsrow[i];
            F4U hv0; hv0.v = h4[32 + i];
            a0 = ffma2(wv0.u[0], hv0.u[0], a0);
            a1 = ffma2(wv0.u[1], hv0.u[1], a1);
            F4U wv1; wv1.v = wsrow[i+1];
            F4U hv1; hv1.v = h4[33 + i];
            a2 = ffma2(wv1.u[0], hv1.u[0], a2);
            a3 = ffma2(wv1.u[1], hv1.u[1], a3);
        }

        float2 s0 = up2(a0), s1 = up2(a1), s2 = up2(a2), s3 = up2(a3);
        float sum = ((s0.x + s0.y) + (s1.x + s1.y))
                  + ((s2.x + s2.y) + (s3.x + s3.y)) + xv;
        float h = tanhf(sum);

        hbuf[cur ^ 1][j] = h;
        optr[(size_t)t * stride] = h;
        __syncthreads();
        if (prog_out && j == 0) {
            __threadfence();
            st_rel(prog_out, t + 1);
        }
        cur ^= 1;
    }
}

// ---------------------------------------------------------------------------
// Persistent pipeline: 148 CTAs.
//   0..63   : layer-1 scan (xp0 -> h1), publishes g_prog1
//   64..127 : layer-2 scan (xp1 -> out), polls g_midflag
//   128..147: xp1 GEMM workers (h1 @ W_ih1^T + bias), publish g_midflag
// ---------------------------------------------------------------------------
__global__ __launch_bounds__(256, 1) void pipeline_kernel(
    const float* __restrict__ W_hh0,
    const float* __restrict__ W_ih1,
    const float* __restrict__ b_ih1,
    const float* __restrict__ b_hh1,
    const float* __restrict__ W_hh1,
    float* __restrict__ out)
{
    extern __shared__ char smraw[];
    const int bid = blockIdx.x;

    if (bid < 64) {
        scan_role(g_buf0, W_hh0, g_buf1, bid, &g_prog1[bid], nullptr,
                  reinterpret_cast<float4*>(smraw));
    } else if (bid < 128) {
        scan_role(g_buf2, W_hh1, out, bid - 64, nullptr, g_midflag,
                  reinterpret_cast<float4*>(smraw));
    } else {
        const int wid = bid - 128;
        const int tid = threadIdx.x;
        for (int w = wid; w < NTILE; w += NGW) {
            int c  = w >> 1;
            int bn = (w & 1) * 128;
            if (tid < BATCH)
                while (ld_acq(&g_prog1[tid]) < 2 * c + 2) __nanosleep(200);
            __syncthreads();
            gemm_tile128(g_buf1 + (size_t)c * 128 * 256, W_ih1, b_ih1, b_hh1,
                         g_buf2 + (size_t)c * 128 * 256, bn, smraw);
            __syncthreads();
            if (tid == 0) {
                __threadfence();
                st_rel(&g_midflag[w], 1);
            }
        }
    }
}

// ---------------------------------------------------------------------------
extern "C" void kernel_launch(void* const* d_in, const int* in_sizes, int n_in,
                              void* d_out, int out_size)
{
    const float* x     = (const float*)d_in[0];
    const float* W_ih0 = (const float*)d_in[1];
    const float* W_hh0 = (const float*)d_in[2];
    const float* b_ih0 = (const float*)d_in[3];
    const float* b_hh0 = (const float*)d_in[4];
    const float* W_ih1 = (const float*)d_in[5];
    const float* W_hh1 = (const float*)d_in[6];
    const float* b_ih1 = (const float*)d_in[7];
    const float* b_hh1 = (const float*)d_in[8];
    float* out = (float*)d_out;

    float* buf0;
    cudaGetSymbolAddress((void**)&buf0, g_buf0);

    const int PIPE_SMEM = 256 * 33 * 16;  // 135168 B (scan Wt; >= GEMM_SMEM)
    cudaFuncSetAttribute(pipeline_kernel,
                         cudaFuncAttributeMaxDynamicSharedMemorySize, PIPE_SMEM);
    cudaFuncSetAttribute(gemm_bias_kernel,
                         cudaFuncAttributeMaxDynamicSharedMemorySize, GEMM_SMEM);

    zero_flags_kernel<<<1, 256>>>();

    // Phase A: xp0 = x @ W_ih0^T + (b_ih0 + b_hh0)
    gemm_bias_kernel<<<dim3(NCHUNK, 2), 256, GEMM_SMEM>>>(
        x, W_ih0, b_ih0, b_hh0, buf0);

    // Phases B/C/D fused: persistent pipeline across 148 SMs
    pipeline_kernel<<<148, 256, PIPE_SMEM>>>(W_hh0, W_ih1, b_ih1, b_hh1,
                                             W_hh1, out);
}

// round 7
// speedup vs baseline: 1.4683x; 1.4683x over previous
#include <cuda_runtime.h>
#include <cuda_bf16.h>
#include <cstdint>

#define T_STEPS 2048
#define BATCH   64
#define HID     256
#define MROWS   (T_STEPS * BATCH)   // 131072
#define NGW     20
#define NSTREAM 10
#define NCHUNK  1024                // 128-row chunks
#define NTILE   (NCHUNK * 2)

// GEMM smem layout (bytes)
#define SM_BIAS  0
#define SM_WHI   1024
#define WROWB    264                 // bf16 per W smem row (256 + 8 pad)
#define WBYTES   (128 * WROWB * 2)   // 67584
#define SM_WLO   (SM_WHI + WBYTES)
#define SM_AHI   (SM_WLO + WBYTES)   // 136192
#define AROWB    72                  // bf16 per A smem row (64 + 8 pad)
#define ABYTES   (128 * AROWB * 2)   // 18432
#define SM_ALO   (SM_AHI + ABYTES)
#define GEMM_SMEM (SM_ALO + ABYTES)  // 173056
#define PIPE_SMEM GEMM_SMEM          // >= scan's 135168

__device__ float g_buf0[(size_t)MROWS * HID];   // xp0 fp32
__device__ float g_buf2[(size_t)MROWS * HID];   // xp1 fp32
__device__ __nv_bfloat16 g_xhi[(size_t)MROWS * HID];
__device__ __nv_bfloat16 g_xlo[(size_t)MROWS * HID];
__device__ __nv_bfloat16 g_h1hi[(size_t)MROWS * HID];
__device__ __nv_bfloat16 g_h1lo[(size_t)MROWS * HID];
__device__ __nv_bfloat16 g_Whi[2][HID * HID];   // [mat][n*256+k]
__device__ __nv_bfloat16 g_Wlo[2][HID * HID];
__device__ int g_prog1[BATCH];
__device__ int g_midflag[NTILE];

// ---------------------------------------------------------------------------
union F4U { float4 v; unsigned long long u[2]; };
__device__ __forceinline__ unsigned long long ffma2(
    unsigned long long a, unsigned long long b, unsigned long long c)
{
    unsigned long long d;
    asm("fma.rn.f32x2 %0, %1, %2, %3;" : "=l"(d) : "l"(a), "l"(b), "l"(c));
    return d;
}
__device__ __forceinline__ float2 up2(unsigned long long v)
{
    float2 r;
    asm("mov.b64 {%0, %1}, %2;" : "=f"(r.x), "=f"(r.y) : "l"(v));
    return r;
}
__device__ __forceinline__ int ld_acq(const int* p)
{
    int v;
    asm volatile("ld.acquire.gpu.global.b32 %0, [%1];" : "=r"(v) : "l"(p) : "memory");
    return v;
}
__device__ __forceinline__ void st_rel(int* p, int v)
{
    asm volatile("st.release.gpu.global.b32 [%0], %1;" :: "l"(p), "r"(v) : "memory");
}

#define MMA_BF16(d, a, b) \
    asm volatile("mma.sync.aligned.m16n8k16.row.col.f32.bf16.bf16.f32 " \
        "{%0,%1,%2,%3},{%4,%5,%6,%7},{%8,%9},{%0,%1,%2,%3};" \
        : "+f"((d)[0]), "+f"((d)[1]), "+f"((d)[2]), "+f"((d)[3]) \
        : "r"((a)[0]), "r"((a)[1]), "r"((a)[2]), "r"((a)[3]), \
          "r"((b)[0]), "r"((b)[1]))

// ---------------------------------------------------------------------------
// Prep: zero flags, convert W_ih0/W_ih1 and x to bf16 hi/lo.
// ---------------------------------------------------------------------------
__global__ void prep_kernel(const float* __restrict__ x,
                            const float* __restrict__ Wih0,
                            const float* __restrict__ Wih1)
{
    int idx = blockIdx.x * blockDim.x + threadIdx.x;
    int nthr = gridDim.x * blockDim.x;
    if (blockIdx.x == 0) {
        int t = threadIdx.x;
        if (t < BATCH) g_prog1[t] = 0;
        for (int i = t; i < NTILE; i += blockDim.x) g_midflag[i] = 0;
    }
    for (int i = idx; i < 2 * HID * HID; i += nthr) {
        int m = i >> 16, e = i & 0xFFFF;
        float w = (m == 0 ? Wih0 : Wih1)[e];
        __nv_bfloat16 hi = __float2bfloat16(w);
        g_Whi[m][e] = hi;
        g_Wlo[m][e] = __float2bfloat16(w - __bfloat162float(hi));
    }
    for (size_t i = idx; i < (size_t)MROWS * HID; i += nthr) {
        float v = x[i];
        __nv_bfloat16 hi = __float2bfloat16(v);
        g_xhi[i] = hi;
        g_xlo[i] = __float2bfloat16(v - __bfloat162float(hi));
    }
}

// ---------------------------------------------------------------------------
// Stage W half [bn..bn+128) hi/lo + bias into smem (once per CTA).
// ---------------------------------------------------------------------------
__device__ __forceinline__ void mma_setup_w(
    char* sm, const __nv_bfloat16* Whig, const __nv_bfloat16* Wlog, int bn,
    const float* b1, const float* b2)
{
    const int tid = threadIdx.x;
    const int row = tid >> 1;            // 0..127
    const int seg = tid & 1;             // 128-bf16 half of a row
    const uint4* ghi = reinterpret_cast<const uint4*>(
        Whig + (size_t)(bn + row) * 256 + seg * 128);
    const uint4* glo = reinterpret_cast<const uint4*>(
        Wlog + (size_t)(bn + row) * 256 + seg * 128);
    uint4* shi = reinterpret_cast<uint4*>(sm + SM_WHI + row * (WROWB*2) + seg * 256);
    uint4* slo = reinterpret_cast<uint4*>(sm + SM_WLO + row * (WROWB*2) + seg * 256);
    #pragma unroll
    for (int q = 0; q < 16; q++) { shi[q] = ghi[q]; slo[q] = glo[q]; }
    if (tid < 128) {
        int n = bn + tid;
        reinterpret_cast<float*>(sm + SM_BIAS)[tid] = b1[n] + b2[n];
    }
    __syncthreads();
}

// ---------------------------------------------------------------------------
// One 128x128 tile: C[128 rows][bn..bn+128) = A(hi+lo) . W(hi+lo)^T + bias
// A given as global bf16 hi/lo row blocks (rows x 256). 256 thr, 8 warps 4x2.
// ---------------------------------------------------------------------------
__device__ __forceinline__ void mma_tile(
    const __nv_bfloat16* __restrict__ Ahig,
    const __nv_bfloat16* __restrict__ Alog,
    float* __restrict__ Crows, int bn, char* sm)
{
    const int tid  = threadIdx.x;
    const int lane = tid & 31;
    const int wid  = tid >> 5;
    const int g    = lane >> 2;
    const int tig  = lane & 3;
    const int m_base = (wid >> 1) * 32;
    const int n_base = (wid & 1) * 64;

    const uint32_t* Wwhi = reinterpret_cast<const uint32_t*>(sm + SM_WHI);
    const uint32_t* Wwlo = reinterpret_cast<const uint32_t*>(sm + SM_WLO);
    const uint32_t* Awhi = reinterpret_cast<const uint32_t*>(sm + SM_AHI);
    const uint32_t* Awlo = reinterpret_cast<const uint32_t*>(sm + SM_ALO);

    float acc[2][8][4];
    #pragma unroll
    for (int mf = 0; mf < 2; mf++)
        #pragma unroll
        for (int nf = 0; nf < 8; nf++)
            #pragma unroll
            for (int q = 0; q < 4; q++) acc[mf][nf][q] = 0.f;

    const int arow = tid >> 1;           // A stage: row
    const int aseg = tid & 1;            // 32-bf16 half of 64-wide chunk

    for (int kc = 0; kc < 4; kc++) {
        __syncthreads();   // previous iteration's frag reads complete
        // stage A chunk (128 rows x 64 k) hi/lo
        {
            const uint4* ghi = reinterpret_cast<const uint4*>(
                Ahig + (size_t)arow * 256 + kc * 64 + aseg * 32);
            const uint4* glo = reinterpret_cast<const uint4*>(
                Alog + (size_t)arow * 256 + kc * 64 + aseg * 32);
            uint4* shi = reinterpret_cast<uint4*>(sm + SM_AHI + arow * (AROWB*2) + aseg * 64);
            uint4* slo = reinterpret_cast<uint4*>(sm + SM_ALO + arow * (AROWB*2) + aseg * 64);
            #pragma unroll
            for (int q = 0; q < 4; q++) { shi[q] = ghi[q]; slo[q] = glo[q]; }
        }
        __syncthreads();

        #pragma unroll
        for (int ks = 0; ks < 4; ks++) {
            const int kwl = ks * 8;                     // k word in A chunk
            const int kwg = kc * 32 + ks * 8;           // k word in W rows
            uint32_t ahi[2][4], alo[2][4], bhi[8][2], blo[8][2];
            #pragma unroll
            for (int mf = 0; mf < 2; mf++) {
                int r0 = (m_base + mf * 16 + g) * 36 + kwl + tig;
                int r1 = r0 + 8 * 36;
                ahi[mf][0] = Awhi[r0];     ahi[mf][1] = Awhi[r1];
                ahi[mf][2] = Awhi[r0 + 4]; ahi[mf][3] = Awhi[r1 + 4];
                alo[mf][0] = Awlo[r0];     alo[mf][1] = Awlo[r1];
                alo[mf][2] = Awlo[r0 + 4]; alo[mf][3] = Awlo[r1 + 4];
            }
            #pragma unroll
            for (int nf = 0; nf < 8; nf++) {
                int rb = (n_base + nf * 8 + g) * 132 + kwg + tig;
                bhi[nf][0] = Wwhi[rb]; bhi[nf][1] = Wwhi[rb + 4];
                blo[nf][0] = Wwlo[rb]; blo[nf][1] = Wwlo[rb + 4];
            }
            #pragma unroll
            for (int mf = 0; mf < 2; mf++)
                #pragma unroll
                for (int nf = 0; nf < 8; nf++) {
                    MMA_BF16(acc[mf][nf], ahi[mf], bhi[nf]);
                    MMA_BF16(acc[mf][nf], ahi[mf], blo[nf]);
                    MMA_BF16(acc[mf][nf], alo[mf], bhi[nf]);
                }
        }
    }

    const float* bias = reinterpret_cast<const float*>(sm + SM_BIAS);
    #pragma unroll
    for (int mf = 0; mf < 2; mf++) {
        int row0 = m_base + mf * 16 + g;
        #pragma unroll
        for (int nf = 0; nf < 8; nf++) {
            int col = n_base + nf * 8 + tig * 2;
            float2 o0 = { acc[mf][nf][0] + bias[col],
                          acc[mf][nf][1] + bias[col + 1] };
            float2 o1 = { acc[mf][nf][2] + bias[col],
                          acc[mf][nf][3] + bias[col + 1] };
            *reinterpret_cast<float2*>(&Crows[(size_t)row0 * 256 + bn + col]) = o0;
            *reinterpret_cast<float2*>(&Crows[(size_t)(row0 + 8) * 256 + bn + col]) = o1;
        }
    }
}

// ---------------------------------------------------------------------------
// Phase A: xp0 = x @ W_ih0^T + bias (tensor path), 148 persistent CTAs.
// ---------------------------------------------------------------------------
__global__ __launch_bounds__(256, 1) void phase_a_kernel(
    const float* __restrict__ b_ih0, const float* __restrict__ b_hh0)
{
    extern __shared__ char sm[];
    const int half = blockIdx.x & 1;
    const int stream = blockIdx.x >> 1;   // 0..73
    const int bn = half * 128;
    mma_setup_w(sm, g_Whi[0], g_Wlo[0], bn, b_ih0, b_hh0);
    for (int c = stream; c < NCHUNK; c += 74)
        mma_tile(g_xhi + (size_t)c * 128 * 256, g_xlo + (size_t)c * 128 * 256,
                 g_buf0 + (size_t)c * 128 * 256, bn, sm);
}

// ---------------------------------------------------------------------------
// Scan role. layer1 mode: write h as bf16 hi/lo + publish progress.
// layer2 mode: poll tile flags, write fp32 out.
// ---------------------------------------------------------------------------
__device__ __forceinline__ void scan_role(
    const float* __restrict__ xp, const float* __restrict__ Whh,
    int b, float4* Wt,
    __nv_bfloat16* outhi, __nv_bfloat16* outlo, int* prog_out,   // layer1
    float* outf, const int* poll_flags)                           // layer2
{
    __shared__ __align__(16) float hbuf[2][HID];
    const int j = threadIdx.x;

    unsigned long long w2[64];
    const float4* wrow = reinterpret_cast<const float4*>(Whh + (size_t)j * HID);
    #pragma unroll
    for (int i = 0; i < 32; i++) {
        F4U v; v.v = wrow[i];
        w2[2*i] = v.u[0]; w2[2*i+1] = v.u[1];
    }
    #pragma unroll
    for (int i = 0; i < 32; i++)
        Wt[j * 33 + i] = wrow[32 + i];

    hbuf[0][j] = 0.f;
    __syncthreads();

    const float4* wsrow  = &Wt[j * 33];
    const size_t  stride = (size_t)BATCH * HID;
    const size_t  base   = (size_t)b * HID + j;

    int cur = 0;
    for (int t = 0; t < T_STEPS; t++) {
        if (poll_flags && (t & 1) == 0) {
            int c = t >> 1;
            if (j < 2)
                while (ld_acq(&poll_flags[c * 2 + j]) == 0) __nanosleep(100);
            __syncthreads();
        }

        float xv = xp[(size_t)t * stride + base];

        const float4* h4 = reinterpret_cast<const float4*>(hbuf[cur]);
        unsigned long long a0 = 0ull, a1 = 0ull, a2 = 0ull, a3 = 0ull;

        #pragma unroll
        for (int i = 0; i < 32; i += 2) {
            F4U hv0; hv0.v = h4[i];
            a0 = ffma2(w2[2*i],   hv0.u[0], a0);
            a1 = ffma2(w2[2*i+1], hv0.u[1], a1);
            F4U hv1; hv1.v = h4[i+1];
            a2 = ffma2(w2[2*i+2], hv1.u[0], a2);
            a3 = ffma2(w2[2*i+3], hv1.u[1], a3);
        }
        #pragma unroll
        for (int i = 0; i < 32; i += 2) {
            F4U wv0; wv0.v = wsrow[i];
            F4U hv0; hv0.v = h4[32 + i];
            a0 = ffma2(wv0.u[0], hv0.u[0], a0);
            a1 = ffma2(wv0.u[1], hv0.u[1], a1);
            F4U wv1; wv1.v = wsrow[i+1];
            F4U hv1; hv1.v = h4[33 + i];
            a2 = ffma2(wv1.u[0], hv1.u[0], a2);
            a3 = ffma2(wv1.u[1], hv1.u[1], a3);
        }

        float2 s0 = up2(a0), s1 = up2(a1), s2 = up2(a2), s3 = up2(a3);
        float sum = ((s0.x + s0.y) + (s1.x + s1.y))
                  + ((s2.x + s2.y) + (s3.x + s3.y)) + xv;
        float h = tanhf(sum);

        hbuf[cur ^ 1][j] = h;
        if (outf) {
            outf[(size_t)t * stride + base] = h;
        } else {
            __nv_bfloat16 hv = __float2bfloat16(h);
            outhi[(size_t)t * stride + base] = hv;
            outlo[(size_t)t * stride + base] =
                __float2bfloat16(h - __bfloat162float(hv));
        }
        __syncthreads();
        if (prog_out && j == 0) st_rel(prog_out, t + 1);
        cur ^= 1;
    }
}

// ---------------------------------------------------------------------------
// Persistent pipeline: 148 CTAs.
//   0..63   : layer-1 scan -> h1 (bf16 hi/lo), publishes g_prog1
//   64..127 : layer-2 scan (xp1) -> out fp32, polls g_midflag
//   128..147: HMMA xp1 workers (h1 @ W_ih1^T + bias) -> g_buf2
// ---------------------------------------------------------------------------
__global__ __launch_bounds__(256, 1) void pipeline_kernel(
    const float* __restrict__ W_hh0,
    const float* __restrict__ b_ih1,
    const float* __restrict__ b_hh1,
    const float* __restrict__ W_hh1,
    float* __restrict__ out)
{
    extern __shared__ char smraw[];
    const int bid = blockIdx.x;

    if (bid < 64) {
        scan_role(g_buf0, W_hh0, bid, reinterpret_cast<float4*>(smraw),
                  g_h1hi, g_h1lo, &g_prog1[bid], nullptr, nullptr);
    } else if (bid < 128) {
        scan_role(g_buf2, W_hh1, bid - 64, reinterpret_cast<float4*>(smraw),
                  nullptr, nullptr, nullptr, out, g_midflag);
    } else {
        const int w = bid - 128;
        const int half = w & 1;
        const int stream = w >> 1;        // 0..9
        const int bn = half * 128;
        const int tid = threadIdx.x;

        mma_setup_w(smraw, g_Whi[1], g_Wlo[1], bn, b_ih1, b_hh1);
        for (int c = stream; c < NCHUNK; c += NSTREAM) {
            if (tid < BATCH)
                while (ld_acq(&g_prog1[tid]) < 2 * c + 2) __nanosleep(200);
            __syncthreads();
            mma_tile(g_h1hi + (size_t)c * 128 * 256,
                     g_h1lo + (size_t)c * 128 * 256,
                     g_buf2 + (size_t)c * 128 * 256, bn, smraw);
            __syncthreads();
            if (tid == 0) st_rel(&g_midflag[c * 2 + half], 1);
        }
    }
}

// ---------------------------------------------------------------------------
extern "C" void kernel_launch(void* const* d_in, const int* in_sizes, int n_in,
                              void* d_out, int out_size)
{
    const float* x     = (const float*)d_in[0];
    const float* W_ih0 = (const float*)d_in[1];
    const float* W_hh0 = (const float*)d_in[2];
    const float* b_ih0 = (const float*)d_in[3];
    const float* b_hh0 = (const float*)d_in[4];
    const float* W_ih1 = (const float*)d_in[5];
    const float* W_hh1 = (const float*)d_in[6];
    const float* b_ih1 = (const float*)d_in[7];
    const float* b_hh1 = (const float*)d_in[8];
    float* out = (float*)d_out;

    cudaFuncSetAttribute(phase_a_kernel,
                         cudaFuncAttributeMaxDynamicSharedMemorySize, GEMM_SMEM);
    cudaFuncSetAttribute(pipeline_kernel,
                         cudaFuncAttributeMaxDynamicSharedMemorySize, PIPE_SMEM);

    prep_kernel<<<1024, 256>>>(x, W_ih0, W_ih1);
    phase_a_kernel<<<148, 256, GEMM_SMEM>>>(b_ih0, b_hh0);
    pipeline_kernel<<<148, 256, PIPE_SMEM>>>(W_hh0, b_ih1, b_hh1, W_hh1, out);
}